// round 1
// baseline (speedup 1.0000x reference)
#include <cuda_runtime.h>

// 512x512 Jacobi (4-neighbor average, zero-Dirichlet mask) iterated 1000x.
// Strategy: single persistent kernel. 128 CTAs (all co-resident on 148 SMs),
// each CTA owns 4 rows of the grid ENTIRELY IN REGISTERS (128 threads x
// float4 columns = 512 cols). Lateral neighbors via warp shuffle + tiny smem
// for warp seams; vertical halos (2 rows per CTA) exchanged through L2 with
// __stcg/__ldcg (L1 bypass: L1 is NOT flushed inside a persistent kernel);
// one grid-wide epoch barrier per iteration (atomicAdd + volatile spin).
//
// Arithmetic order matches the reference exactly:
//   xn = 0.25f * (((up + down) + left) + right), mask boundary to 0 after.
// Iteration 1 must read the UNMASKED x0 boundary values — boundary cells are
// held in registers like interior cells and only the step OUTPUT is masked.

#define HH   512
#define WW   512
#define NT   1000
#define NCTA 128            // <= 148 SMs -> all CTAs resident, barrier is safe
#define RPC  4              // rows per CTA (128*4 = 512)
#define TPB  128            // threads per CTA; each thread owns 4 columns

struct BarState { unsigned count; unsigned epoch; };
__device__ BarState g_bar;                         // zeroed by kernel_launch
__device__ float g_halo[2][NCTA][2][WW];           // [parity][cta][top/bot][col]

__device__ __forceinline__ void grid_barrier(unsigned target_epoch) {
    __syncthreads();
    if (threadIdx.x == 0) {
        __threadfence();                            // publish halos before arrive
        unsigned old = atomicAdd(&g_bar.count, 1u);
        if (old == NCTA - 1u) {
            g_bar.count = 0u;                       // all arrived; only we touch it
            __threadfence();
            atomicExch(&g_bar.epoch, target_epoch); // release
        } else {
            volatile unsigned* e = &g_bar.epoch;
            while (*e < target_epoch) { }
            __threadfence();                        // acquire
        }
    }
    __syncthreads();
}

__global__ void __launch_bounds__(TPB, 1)
jacobi_persist(const float* __restrict__ X, const float* __restrict__ Y,
               float* __restrict__ out) {
    const int cta  = blockIdx.x;
    const int tid  = threadIdx.x;
    const int lane = tid & 31;
    const int warp = tid >> 5;
    const int col  = tid * 4;          // first of this thread's 4 columns
    const int row0 = cta * RPC;

    __shared__ float sFirst[RPC][4];   // warp w lane0  .x  -> left seam of warp w
    __shared__ float sLast [RPC][4];   // warp w lane31 .w  -> right seam of warp w

    // ---- initial condition: x0 = exp(-50*((X-.5)^2 + (Y-.5)^2)), unmasked ----
    float4 cur[RPC];
#pragma unroll
    for (int r = 0; r < RPC; r++) {
        const float4 xv = *(const float4*)(X + (size_t)(row0 + r) * WW + col);
        const float4 yv = *(const float4*)(Y + (size_t)(row0 + r) * WW + col);
        float4 v;
        { float dx = xv.x - 0.5f, dy = yv.x - 0.5f; v.x = expf(-50.0f * (dx*dx + dy*dy)); }
        { float dx = xv.y - 0.5f, dy = yv.y - 0.5f; v.y = expf(-50.0f * (dx*dx + dy*dy)); }
        { float dx = xv.z - 0.5f, dy = yv.z - 0.5f; v.z = expf(-50.0f * (dx*dx + dy*dy)); }
        { float dx = xv.w - 0.5f, dy = yv.w - 0.5f; v.w = expf(-50.0f * (dx*dx + dy*dy)); }
        cur[r] = v;
    }

    // publish x0 edge rows into parity-0 halo, then sync the grid
    unsigned p = 0;
    __stcg((float4*)&g_halo[0][cta][0][col], cur[0]);
    __stcg((float4*)&g_halo[0][cta][1][col], cur[RPC - 1]);
    unsigned epoch = 1;
    grid_barrier(epoch++);

    const float4 zero4 = make_float4(0.f, 0.f, 0.f, 0.f);

    for (int t = 0; t < NT; ++t) {
        // vertical halos of the CURRENT state (published last iteration)
        float4 above = zero4, below = zero4;
        if (cta > 0)        above = __ldcg((const float4*)&g_halo[p][cta - 1][1][col]);
        if (cta < NCTA - 1) below = __ldcg((const float4*)&g_halo[p][cta + 1][0][col]);

        // lateral warp-seam exchange via smem (barrier's syncthreads protects reuse)
#pragma unroll
        for (int r = 0; r < RPC; r++) {
            if (lane == 0)  sFirst[r][warp] = cur[r].x;
            if (lane == 31) sLast [r][warp] = cur[r].w;
        }
        __syncthreads();

        float4 nxt[RPC];
#pragma unroll
        for (int r = 0; r < RPC; r++) {
            const float4 up = (r == 0)       ? above : cur[r - 1];
            const float4 dn = (r == RPC - 1) ? below : cur[r + 1];
            float lN = __shfl_up_sync(0xffffffffu, cur[r].w, 1);
            if (lane == 0)  lN = (warp > 0) ? sLast[r][warp - 1] : 0.0f;   // col-1 pad
            float rN = __shfl_down_sync(0xffffffffu, cur[r].x, 1);
            if (lane == 31) rN = (warp < 3) ? sFirst[r][warp + 1] : 0.0f;  // col+1 pad
            float4 n;
            n.x = 0.25f * (((up.x + dn.x) + lN)       + cur[r].y);
            n.y = 0.25f * (((up.y + dn.y) + cur[r].x) + cur[r].z);
            n.z = 0.25f * (((up.z + dn.z) + cur[r].y) + cur[r].w);
            n.w = 0.25f * (((up.w + dn.w) + cur[r].z) + rN);
            nxt[r] = n;
        }

        // boundary mask (rows/cols 0 and 511 -> 0)
        if (tid == 0)       { nxt[0].x = 0.f; nxt[1].x = 0.f; nxt[2].x = 0.f; nxt[3].x = 0.f; }
        if (tid == TPB - 1) { nxt[0].w = 0.f; nxt[1].w = 0.f; nxt[2].w = 0.f; nxt[3].w = 0.f; }
        if (cta == 0)        nxt[0]       = zero4;
        if (cta == NCTA - 1) nxt[RPC - 1] = zero4;

#pragma unroll
        for (int r = 0; r < RPC; r++) cur[r] = nxt[r];

        // publish new edge rows into the other parity, then grid barrier
        p ^= 1u;
        __stcg((float4*)&g_halo[p][cta][0][col], cur[0]);
        __stcg((float4*)&g_halo[p][cta][1][col], cur[RPC - 1]);
        grid_barrier(epoch++);
    }

    // final state -> output (N=C=1, contiguous 512x512)
#pragma unroll
    for (int r = 0; r < RPC; r++)
        *(float4*)(out + (size_t)(row0 + r) * WW + col) = cur[r];
}

extern "C" void kernel_launch(void* const* d_in, const int* in_sizes, int n_in,
                              void* d_out, int out_size) {
    (void)in_sizes; (void)n_in; (void)out_size;
    // reset barrier state every call so graph replays are deterministic
    void* barAddr = nullptr;
    cudaGetSymbolAddress(&barAddr, g_bar);
    cudaMemsetAsync(barAddr, 0, sizeof(BarState));
    jacobi_persist<<<NCTA, TPB>>>((const float*)d_in[0], (const float*)d_in[1],
                                  (float*)d_out);
}

// round 2
// speedup vs baseline: 1.5110x; 1.5110x over previous
#include <cuda_runtime.h>

// 512x512 Jacobi (4-neighbor avg, zero-Dirichlet mask) x1000, persistent kernel.
// Round 2: replace the centralized grid barrier (atomicAdd + fences + spin, ~4400
// cyc/iter) with PER-THREAD point-to-point neighbor synchronization:
//   thread t of CTA i reads exactly the float4 written by thread t of CTA i+-1,
//   so each thread publishes its halo slice (__stcg) and st.release.gpu's an
//   epoch flag; the matching neighbor thread ld.acquire.gpu-polls it.
// Interior rows (1,2) and all lateral terms are computed BEFORE polling, so most
// compute hides under the flag round-trip. Exact reference arithmetic order
// ((up+dn)+l)+r is preserved (first add is commutative => bitwise identical).

#define HH   512
#define WW   512
#define NT   1000
#define NCTA 128            // <= 148 SMs -> all CTAs co-resident (no deadlock)
#define RPC  4              // rows per CTA
#define TPB  128            // each thread owns 4 columns (float4)

__device__ float    g_halo[2][NCTA][2][WW];   // [parity][cta][top/bot][col]
__device__ unsigned g_flag[NCTA][TPB];        // per-thread epoch flags

__device__ __forceinline__ unsigned ld_acq(const unsigned* p) {
    unsigned v;
    asm volatile("ld.acquire.gpu.u32 %0, [%1];" : "=r"(v) : "l"(p) : "memory");
    return v;
}
__device__ __forceinline__ void st_rel(unsigned* p, unsigned v) {
    asm volatile("st.release.gpu.u32 [%0], %1;" :: "l"(p), "r"(v) : "memory");
}

__global__ void __launch_bounds__(TPB, 1)
jacobi_p2p(const float* __restrict__ X, const float* __restrict__ Y,
           float* __restrict__ out) {
    const int cta  = blockIdx.x;
    const int tid  = threadIdx.x;
    const int lane = tid & 31;
    const int warp = tid >> 5;
    const int col  = tid * 4;
    const int row0 = cta * RPC;

    __shared__ float sFirst[RPC][4];   // lane0 .x of each warp (left seam)
    __shared__ float sLast [RPC][4];   // lane31 .w of each warp (right seam)

    // ---- x0 = exp(-50*((X-.5)^2+(Y-.5)^2)), UNMASKED ----
    float4 cur[RPC];
#pragma unroll
    for (int r = 0; r < RPC; r++) {
        const float4 xv = *(const float4*)(X + (size_t)(row0 + r) * WW + col);
        const float4 yv = *(const float4*)(Y + (size_t)(row0 + r) * WW + col);
        float4 v;
        { float dx = xv.x - 0.5f, dy = yv.x - 0.5f; v.x = expf(-50.0f * (dx*dx + dy*dy)); }
        { float dx = xv.y - 0.5f, dy = yv.y - 0.5f; v.y = expf(-50.0f * (dx*dx + dy*dy)); }
        { float dx = xv.z - 0.5f, dy = yv.z - 0.5f; v.z = expf(-50.0f * (dx*dx + dy*dy)); }
        { float dx = xv.w - 0.5f, dy = yv.w - 0.5f; v.w = expf(-50.0f * (dx*dx + dy*dy)); }
        cur[r] = v;
    }

    // publish state-0 edges into parity 0, flag epoch 1 (per-thread release)
    __stcg((float4*)&g_halo[0][cta][0][col], cur[0]);
    __stcg((float4*)&g_halo[0][cta][1][col], cur[RPC - 1]);
    st_rel(&g_flag[cta][tid], 1u);

    const unsigned* flagUp = (cta > 0)        ? &g_flag[cta - 1][tid] : 0;
    const unsigned* flagDn = (cta < NCTA - 1) ? &g_flag[cta + 1][tid] : 0;
    const float4 zero4 = make_float4(0.f, 0.f, 0.f, 0.f);

    for (int t = 0; t < NT; ++t) {
        const unsigned p = (unsigned)t & 1u;

        __syncthreads();                 // smem reuse guard (prev iter readers)
#pragma unroll
        for (int r = 0; r < RPC; r++) {
            if (lane == 0)  sFirst[r][warp] = cur[r].x;
            if (lane == 31) sLast [r][warp] = cur[r].w;
        }
        __syncthreads();

        // lateral neighbors for all rows (CTA-local, no waiting)
        float lN[RPC], rN[RPC];
#pragma unroll
        for (int r = 0; r < RPC; r++) {
            lN[r] = __shfl_up_sync(0xffffffffu, cur[r].w, 1);
            if (lane == 0)  lN[r] = (warp > 0) ? sLast[r][warp - 1] : 0.0f;
            rN[r] = __shfl_down_sync(0xffffffffu, cur[r].x, 1);
            if (lane == 31) rN[r] = (warp < 3) ? sFirst[r][warp + 1] : 0.0f;
        }

        // interior rows 1..2: fully computable before the halo arrives
        float4 nxt[RPC];
#pragma unroll
        for (int r = 1; r < RPC - 1; r++) {
            const float4 up = cur[r - 1], dn = cur[r + 1];
            nxt[r].x = 0.25f * (((up.x + dn.x) + lN[r])    + cur[r].y);
            nxt[r].y = 0.25f * (((up.y + dn.y) + cur[r].x) + cur[r].z);
            nxt[r].z = 0.25f * (((up.z + dn.z) + cur[r].y) + cur[r].w);
            nxt[r].w = 0.25f * (((up.w + dn.w) + cur[r].z) + rN[r]);
        }

        // per-thread neighbor wait + halo read (acquire orders the ldcg after it)
        const unsigned e = (unsigned)t + 1u;
        float4 above = zero4, below = zero4;
        if (cta > 0) {
            while (ld_acq(flagUp) < e) { }
            above = __ldcg((const float4*)&g_halo[p][cta - 1][1][col]);
        }
        if (cta < NCTA - 1) {
            while (ld_acq(flagDn) < e) { }
            below = __ldcg((const float4*)&g_halo[p][cta + 1][0][col]);
        }

        // edge rows 0 and 3 (first add commutes: (up+dn)==(dn+up) bitwise)
        {
            const float4 dn = cur[1];
            nxt[0].x = 0.25f * (((above.x + dn.x) + lN[0])    + cur[0].y);
            nxt[0].y = 0.25f * (((above.y + dn.y) + cur[0].x) + cur[0].z);
            nxt[0].z = 0.25f * (((above.z + dn.z) + cur[0].y) + cur[0].w);
            nxt[0].w = 0.25f * (((above.w + dn.w) + cur[0].z) + rN[0]);
        }
        {
            const float4 up = cur[RPC - 2];
            const int r = RPC - 1;
            nxt[r].x = 0.25f * (((up.x + below.x) + lN[r])    + cur[r].y);
            nxt[r].y = 0.25f * (((up.y + below.y) + cur[r].x) + cur[r].z);
            nxt[r].z = 0.25f * (((up.z + below.z) + cur[r].y) + cur[r].w);
            nxt[r].w = 0.25f * (((up.w + below.w) + cur[r].z) + rN[r]);
        }

        // Dirichlet mask (rows/cols 0 and 511)
        if (tid == 0)       { nxt[0].x = 0.f; nxt[1].x = 0.f; nxt[2].x = 0.f; nxt[3].x = 0.f; }
        if (tid == TPB - 1) { nxt[0].w = 0.f; nxt[1].w = 0.f; nxt[2].w = 0.f; nxt[3].w = 0.f; }
        if (cta == 0)        nxt[0]       = zero4;
        if (cta == NCTA - 1) nxt[RPC - 1] = zero4;

#pragma unroll
        for (int r = 0; r < RPC; r++) cur[r] = nxt[r];

        // publish new edges into other parity, release per-thread flag
        __stcg((float4*)&g_halo[p ^ 1u][cta][0][col], cur[0]);
        __stcg((float4*)&g_halo[p ^ 1u][cta][1][col], cur[RPC - 1]);
        st_rel(&g_flag[cta][tid], (unsigned)t + 2u);
    }

#pragma unroll
    for (int r = 0; r < RPC; r++)
        *(float4*)(out + (size_t)(row0 + r) * WW + col) = cur[r];
}

extern "C" void kernel_launch(void* const* d_in, const int* in_sizes, int n_in,
                              void* d_out, int out_size) {
    (void)in_sizes; (void)n_in; (void)out_size;
    // reset epoch flags so every graph replay starts from a clean sync state
    void* flagAddr = nullptr;
    cudaGetSymbolAddress(&flagAddr, g_flag);
    cudaMemsetAsync(flagAddr, 0, sizeof(unsigned) * NCTA * TPB);
    jacobi_p2p<<<NCTA, TPB>>>((const float*)d_in[0], (const float*)d_in[1],
                              (float*)d_out);
}

// round 3
// speedup vs baseline: 23.3286x; 15.4387x over previous
#include <cuda_runtime.h>
#include <math.h>

// JacobiMachine: 1000 steps of masked 4-neighbor Jacobi on 512x512.
// SPECTRAL METHOD: the masked step on the 510x510 interior (zero Dirichlet)
// is diagonalized by DST-I: eigenvalues lam_ij = (cos(pi*i/511)+cos(pi*j/511))/2.
//   x1000 = c * S^T ( lam^999 ⊙ (S x1 S^T) ) S,  c = (2/511)^2
// where x1 = one exact stencil step of x0 (step 1 reads the UNMASKED x0
// boundary; from x1 on the boundary is 0 and the interior operator applies).
// lam^999 < 1e-17 except for modes (i,j) with both indices in [1,64] or both
// in [447,510]  (worst excluded mode: lam=0.9606 -> lam^999 ~ 4e-18).
// => keep 128 modes/dim: I(m) = m+1 (m<64), m+383 (m>=64).
// Pipeline: x0 -> x1 -> T = S*B -> C = T*S^T -> C *= w (double) -> U = S^T*C
// -> C4 = U*S -> output (boundary zeroed). ~167 MFLOP of fp32 GEMM.

#define LDM 512
#define PI_D 3.14159265358979323846

__device__ float g_x0[512 * 512];
__device__ float g_B [512 * 512];   // x1 interior, zero padded to 512x512
__device__ float g_S [128 * 512];   // S[m][k]  = sin(pi*I(m)*(k+1)/511), k<510
__device__ float g_ST[512 * 512];   // ST[k][m] = S[m][k]; rows>=510, cols>=128 = 0
__device__ float g_T [128 * 512];   // S * B
__device__ float g_C [128 * 512];   // T * S^T  (128x128 used), then scaled
__device__ float g_U [512 * 512];   // S^T * C  (cols 0..127 used)
__device__ float g_C4[512 * 512];   // U * S

__device__ __forceinline__ int modeI(int m) { return (m < 64) ? (m + 1) : (m + 383); }

// ---- x0 = exp(-50*((X-.5)^2+(Y-.5)^2)) ----
__global__ void k_init(const float* __restrict__ X, const float* __restrict__ Y) {
    int idx = blockIdx.x * blockDim.x + threadIdx.x;
    if (idx >= 512 * 512) return;
    float dx = X[idx] - 0.5f, dy = Y[idx] - 0.5f;
    g_x0[idx] = expf(-50.0f * (dx * dx + dy * dy));
}

// ---- one masked stencil step: B[k][j] = x1[k+1][j+1] (interior), else 0 ----
__global__ void k_step1(void) {
    int idx = blockIdx.x * blockDim.x + threadIdx.x;
    if (idx >= 512 * 512) return;
    int k = idx >> 9, j = idx & 511;
    float v = 0.0f;
    if (k < 510 && j < 510) {
        int r = k + 1, c = j + 1;   // interior coords in x0
        v = 0.25f * (((g_x0[(r - 1) * 512 + c] + g_x0[(r + 1) * 512 + c])
                      + g_x0[r * 512 + c - 1]) + g_x0[r * 512 + c + 1]);
    }
    g_B[idx] = v;
}

// ---- sine basis (double precision), both S and S^T, with zero padding ----
__global__ void k_basis(void) {
    int idx = blockIdx.x * blockDim.x + threadIdx.x;
    if (idx >= 512 * 512) return;
    int r = idx >> 9, c = idx & 511;
    // ST[r][c]: r = grid index k (0..509 -> interior k+1), c = mode m
    float st = 0.0f;
    if (r < 510 && c < 128)
        st = (float)sin(PI_D * (double)modeI(c) * (double)(r + 1) / 511.0);
    g_ST[idx] = st;
    // S[r][c]: r = mode m (<128), c = grid index k
    if (r < 128) {
        float s = 0.0f;
        if (c < 510)
            s = (float)sin(PI_D * (double)modeI(r) * (double)(c + 1) / 511.0);
        g_S[idx] = s;
    }
}

// ---- scale spectrum: C[m][n] *= (2/511)^2 * lam_{I(m),I(n)}^999 (double) ----
__global__ void k_scale(void) {
    int idx = blockIdx.x * blockDim.x + threadIdx.x;
    if (idx >= 128 * 128) return;
    int m = idx >> 7, n = idx & 127;
    double li  = cos(PI_D * (double)modeI(m) / 511.0);
    double lj  = cos(PI_D * (double)modeI(n) / 511.0);
    double lam = 0.5 * (li + lj);
    double a   = fabs(lam);
    double p   = (a < 1e-300) ? 0.0 : exp(999.0 * log(a));
    if (lam < 0.0) p = -p;                       // 999 is odd
    double w = p * (4.0 / (511.0 * 511.0));
    g_C[m * LDM + n] = (float)((double)g_C[m * LDM + n] * w);
}

// ---- generic tiled GEMM: C[M][N] = A[M][K] * B[K][N], all row-major ld=512.
//      64x64 tiles, 256 threads, 4x4 outputs/thread. M,N,K multiples of 64/16.
__global__ __launch_bounds__(256)
void k_gemm(const float* __restrict__ A, const float* __restrict__ B,
            float* __restrict__ C, int K) {
    __shared__ float As[16][68];   // [k][m], padded for bank spread, 16B-aligned rows
    __shared__ float Bs[16][68];   // [k][n]
    const int tid = threadIdx.x;
    const int tx  = tid & 15, ty = tid >> 4;
    const int mT  = blockIdx.y * 64, nT = blockIdx.x * 64;
    const int arow = tid >> 2, akq = (tid & 3) * 4;   // A loader: row, k-quad
    const int bkk  = tid >> 4, bnn = (tid & 15) * 4;  // B loader: k, n-quad

    float acc[4][4] = {};
    for (int k0 = 0; k0 < K; k0 += 16) {
        float4 a4 = *(const float4*)(A + (size_t)(mT + arow) * LDM + k0 + akq);
        float4 b4 = *(const float4*)(B + (size_t)(k0 + bkk) * LDM + nT + bnn);
        As[akq + 0][arow] = a4.x;
        As[akq + 1][arow] = a4.y;
        As[akq + 2][arow] = a4.z;
        As[akq + 3][arow] = a4.w;
        *(float4*)&Bs[bkk][bnn] = b4;
        __syncthreads();
#pragma unroll
        for (int kk = 0; kk < 16; kk++) {
            float4 av = *(const float4*)&As[kk][ty * 4];
            float4 bv = *(const float4*)&Bs[kk][tx * 4];
            acc[0][0] += av.x * bv.x; acc[0][1] += av.x * bv.y;
            acc[0][2] += av.x * bv.z; acc[0][3] += av.x * bv.w;
            acc[1][0] += av.y * bv.x; acc[1][1] += av.y * bv.y;
            acc[1][2] += av.y * bv.z; acc[1][3] += av.y * bv.w;
            acc[2][0] += av.z * bv.x; acc[2][1] += av.z * bv.y;
            acc[2][2] += av.z * bv.z; acc[2][3] += av.z * bv.w;
            acc[3][0] += av.w * bv.x; acc[3][1] += av.w * bv.y;
            acc[3][2] += av.w * bv.z; acc[3][3] += av.w * bv.w;
        }
        __syncthreads();
    }
#pragma unroll
    for (int i = 0; i < 4; i++)
        *(float4*)(C + (size_t)(mT + ty * 4 + i) * LDM + nT + tx * 4) =
            make_float4(acc[i][0], acc[i][1], acc[i][2], acc[i][3]);
}

// ---- final: out = zero boundary + C4 interior ----
__global__ void k_output(float* __restrict__ out) {
    int idx = blockIdx.x * blockDim.x + threadIdx.x;
    if (idx >= 512 * 512) return;
    int r = idx >> 9, c = idx & 511;
    float v = 0.0f;
    if (r >= 1 && r <= 510 && c >= 1 && c <= 510)
        v = g_C4[(r - 1) * 512 + (c - 1)];
    out[idx] = v;
}

extern "C" void kernel_launch(void* const* d_in, const int* in_sizes, int n_in,
                              void* d_out, int out_size) {
    (void)in_sizes; (void)n_in; (void)out_size;
    const float* X = (const float*)d_in[0];
    const float* Y = (const float*)d_in[1];
    float* out = (float*)d_out;

    float *bS, *bST, *bB, *bT, *bC, *bU, *bC4;
    cudaGetSymbolAddress((void**)&bS,  g_S);
    cudaGetSymbolAddress((void**)&bST, g_ST);
    cudaGetSymbolAddress((void**)&bB,  g_B);
    cudaGetSymbolAddress((void**)&bT,  g_T);
    cudaGetSymbolAddress((void**)&bC,  g_C);
    cudaGetSymbolAddress((void**)&bU,  g_U);
    cudaGetSymbolAddress((void**)&bC4, g_C4);

    const int TB = 256, NE = 512 * 512;
    k_init  <<<(NE + TB - 1) / TB, TB>>>(X, Y);
    k_step1 <<<(NE + TB - 1) / TB, TB>>>();
    k_basis <<<(NE + TB - 1) / TB, TB>>>();
    // T = S * B            (128 x 512, K=512)
    k_gemm<<<dim3(512 / 64, 128 / 64), 256>>>(bS, bB, bT, 512);
    // C = T * S^T          (128 x 128, K=512)
    k_gemm<<<dim3(128 / 64, 128 / 64), 256>>>(bT, bST, bC, 512);
    // C *= (2/511)^2 * lam^999
    k_scale<<<(128 * 128 + TB - 1) / TB, TB>>>();
    // U = S^T * C          (512 x 128, K=128)
    k_gemm<<<dim3(128 / 64, 512 / 64), 256>>>(bST, bC, bU, 128);
    // C4 = U * S           (512 x 512, K=128)
    k_gemm<<<dim3(512 / 64, 512 / 64), 256>>>(bU, bS, bC4, 128);
    k_output<<<(NE + TB - 1) / TB, TB>>>(out);
}

// round 4
// speedup vs baseline: 31.3367x; 1.3433x over previous
#include <cuda_runtime.h>
#include <math.h>

// Spectral solution of 1000 masked-Jacobi steps on 512x512 (zero Dirichlet).
//   out_int = S^T * ( W ⊙ (S * B * S^T) ) * S,  B = interior of one exact
// stencil step of x0 (step 1 reads unmasked x0 boundary), W[m][n] =
// (2/511)^2 * lam^999, lam = (cos(pi*I(m)/511)+cos(pi*I(n)/511))/2.
// Only 128 modes/dim survive lam^999 (I(m)=m+1 for m<64, m+383 else;
// worst dropped mode: lam=0.9606 -> lam^999 ~ 4e-18).
// Round 4: reorder chain so every GEMM has a big dimension (64-128 CTAs),
// fuse everything into 5 launches, integer-exact sinpif basis.
//   P = B*ST (512x128, K=512) ; C = (S*P)⊙W (128x128, K=512)
//   U = C*S  (128x512, K=128) ; out = ST*U (512x512, K=128, shifted store)

#define LDM 512

__device__ float g_B [512 * 512];   // x1 interior (510x510), zero padded
__device__ float g_S [128 * 512];   // S[m][k] = sin(pi*I(m)*(k+1)/511)
__device__ float g_ST[512 * 512];   // ST[k][m] = S[m][k]; zero outside 510x128
__device__ float g_P [512 * 512];   // B * ST   (512x128 used)
__device__ float g_C [128 * 512];   // (S*P)⊙W  (128x128 used)
__device__ float g_U [128 * 512];   // C * S    (128x512)
__device__ float g_W [128 * 128];   // spectral weights

__device__ __forceinline__ int modeI(int m) { return (m < 64) ? (m + 1) : (m + 383); }

__device__ __forceinline__ float x0_at(const float* X, const float* Y, int idx) {
    float dx = X[idx] - 0.5f, dy = Y[idx] - 0.5f;
    return expf(-50.0f * (dx * dx + dy * dy));
}

// One fused prep kernel, tasks partitioned by blockIdx.x (2120 blocks x 256):
//  [0,1024):    B = interior of step1(x0)     (4 expf per element)
//  [1024,2048): sine basis S and ST           (exact int mod + sinpif)
//  [2048,2112): W weights                     (fp64, 16K elems)
//  [2112,2120): zero the boundary of d_out
__global__ void k_prep(const float* __restrict__ X, const float* __restrict__ Y,
                       float* __restrict__ out) {
    const int b = blockIdx.x, tid = threadIdx.x;
    if (b < 1024) {
        int idx = b * 256 + tid;
        int k = idx >> 9, j = idx & 511;
        float v = 0.0f;
        if (k < 510 && j < 510) {
            int r = k + 1, c = j + 1;
            float up = x0_at(X, Y, (r - 1) * 512 + c);
            float dn = x0_at(X, Y, (r + 1) * 512 + c);
            float lf = x0_at(X, Y, r * 512 + c - 1);
            float rt = x0_at(X, Y, r * 512 + c + 1);
            v = 0.25f * (((up + dn) + lf) + rt);   // exact reference order
        }
        g_B[idx] = v;
    } else if (b < 2048) {
        int idx = (b - 1024) * 256 + tid;
        int r = idx >> 9, c = idx & 511;
        float st = 0.0f;
        if (r < 510 && c < 128) {
            int m = (modeI(c) * (r + 1)) % 1022;          // exact reduction
            st = sinpif((float)m * (1.0f / 511.0f));
        }
        g_ST[idx] = st;
        if (r < 128) {
            float s = 0.0f;
            if (c < 510) {
                int m = (modeI(r) * (c + 1)) % 1022;
                s = sinpif((float)m * (1.0f / 511.0f));
            }
            g_S[idx] = s;
        }
    } else if (b < 2112) {
        int idx = (b - 2048) * 256 + tid;      // 0..16383
        int m = idx >> 7, n = idx & 127;
        double li  = cos(3.14159265358979323846 * (double)modeI(m) / 511.0);
        double lj  = cos(3.14159265358979323846 * (double)modeI(n) / 511.0);
        double lam = 0.5 * (li + lj);
        double a   = fabs(lam);
        double p   = (a < 1e-300) ? 0.0 : exp(999.0 * log(a));
        if (lam < 0.0) p = -p;                 // odd power
        g_W[idx] = (float)(p * (4.0 / (511.0 * 511.0)));
    } else {
        int idx = (b - 2112) * 256 + tid;      // 0..2047: four edges of out
        int e = idx >> 9, t = idx & 511;
        if      (e == 0) out[t] = 0.0f;
        else if (e == 1) out[511 * 512 + t] = 0.0f;
        else if (e == 2) out[t * 512] = 0.0f;
        else             out[t * 512 + 511] = 0.0f;
    }
}

// Generic tiled GEMM, all operands row-major ld=512. 256 threads, 16x16 thread
// grid, TM=BM/16 x TN=BN/16 outputs per thread, BK=16.
// EPI: 0 = plain store; 1 = scale by g_W (128x128); 2 = shifted store into out
//      (interior r,c<510 -> out[r+1][c+1]).
template<int BM, int BN, int EPI>
__global__ __launch_bounds__(256)
void k_gemm(const float* __restrict__ A, const float* __restrict__ B,
            float* __restrict__ C, int K) {
    constexpr int TM = BM / 16, TN = BN / 16;
    __shared__ float As[16][BM + 4];   // +4 pad keeps rows 16B-aligned
    __shared__ float Bs[16][BN + 4];
    const int tid = threadIdx.x;
    const int tx = tid & 15, ty = tid >> 4;
    const int mT = blockIdx.y * BM, nT = blockIdx.x * BN;

    float acc[TM][TN] = {};
    for (int k0 = 0; k0 < K; k0 += 16) {
#pragma unroll
        for (int i = tid; i < BM * 16; i += 256) {
            int m = i >> 4, kk = i & 15;
            As[kk][m] = A[(size_t)(mT + m) * LDM + k0 + kk];
        }
#pragma unroll
        for (int i = tid; i < 16 * BN; i += 256) {
            int kk = i / BN, n = i % BN;
            Bs[kk][n] = B[(size_t)(k0 + kk) * LDM + nT + n];
        }
        __syncthreads();
#pragma unroll
        for (int kk = 0; kk < 16; kk++) {
            float av[TM], bv[TN];
#pragma unroll
            for (int i = 0; i < TM; i++) av[i] = As[kk][ty * TM + i];
#pragma unroll
            for (int j = 0; j < TN; j++) bv[j] = Bs[kk][tx * TN + j];
#pragma unroll
            for (int i = 0; i < TM; i++)
#pragma unroll
                for (int j = 0; j < TN; j++) acc[i][j] += av[i] * bv[j];
        }
        __syncthreads();
    }
#pragma unroll
    for (int i = 0; i < TM; i++) {
        int r = mT + ty * TM + i;
#pragma unroll
        for (int j = 0; j < TN; j++) {
            int c = nT + tx * TN + j;
            if (EPI == 0) {
                C[(size_t)r * LDM + c] = acc[i][j];
            } else if (EPI == 1) {
                C[(size_t)r * LDM + c] = acc[i][j] * g_W[r * 128 + c];
            } else {
                if (r < 510 && c < 510)
                    C[(size_t)(r + 1) * 512 + (c + 1)] = acc[i][j];
            }
        }
    }
}

extern "C" void kernel_launch(void* const* d_in, const int* in_sizes, int n_in,
                              void* d_out, int out_size) {
    (void)in_sizes; (void)n_in; (void)out_size;
    const float* X = (const float*)d_in[0];
    const float* Y = (const float*)d_in[1];
    float* out = (float*)d_out;

    float *bB, *bS, *bST, *bP, *bC, *bU;
    cudaGetSymbolAddress((void**)&bB,  g_B);
    cudaGetSymbolAddress((void**)&bS,  g_S);
    cudaGetSymbolAddress((void**)&bST, g_ST);
    cudaGetSymbolAddress((void**)&bP,  g_P);
    cudaGetSymbolAddress((void**)&bC,  g_C);
    cudaGetSymbolAddress((void**)&bU,  g_U);

    k_prep<<<2120, 256>>>(X, Y, out);
    // P = B * ST        (512x128, K=512) — 64 CTAs
    k_gemm<32, 32, 0><<<dim3(128 / 32, 512 / 32), 256>>>(bB, bST, bP, 512);
    // C = (S * P) ⊙ W   (128x128, K=512) — 16 CTAs
    k_gemm<32, 32, 1><<<dim3(128 / 32, 128 / 32), 256>>>(bS, bP, bC, 512);
    // U = C * S         (128x512, K=128) — 64 CTAs
    k_gemm<32, 32, 0><<<dim3(512 / 32, 128 / 32), 256>>>(bC, bS, bU, 128);
    // out = ST * U      (512x512, K=128, shifted) — 128 CTAs
    k_gemm<32, 64, 2><<<dim3(512 / 64, 512 / 32), 256>>>(bST, bU, out, 128);
}

// round 5
// speedup vs baseline: 49.1545x; 1.5686x over previous
#include <cuda_runtime.h>
#include <math.h>

// Spectral solution of 1000 masked-Jacobi steps on 512x512, ONE persistent
// kernel (single graph node, no launch gaps):
//   out_int = S^T * ( W ⊙ (S * B * S^T) ) * S
// B = interior of one exact stencil step of x0 (step 1 reads the unmasked x0
// boundary), W = (2/511)^2 * lam^999, lam=(cos(pi i/511)+cos(pi j/511))/2.
// Only 128 modes/dim survive lam^999: I(m)=m+1 (m<64), m+383 (else).
// Stages (grid barriers between): A) x0/basis/W/out-edges  B) B=stencil(x0)
// C) G1: P=B*S^T split-K2 -> P0,P1 (128 jobs)  D) G2: Cq=S*(P0+P1) split-K4
// (64 jobs, add fused into load)  E) G3: U=((C0+..+C3)⊙W)*S (64 jobs, fused)
// F) G4: out=S^T*U, shifted store (256 jobs).
// Barrier = per-CTA flag slots + CTA0 aggregation; epochs continue across
// graph replays (base read from release word) -> NO per-call reset needed.

#define NCTA 128
#define TPB  256
#define GT   (NCTA * TPB)

__device__ float g_x0[512 * 512];
__device__ float g_B [512 * 512];     // stencil(x0) interior, zero padded
__device__ float g_S [128 * 512];     // S[m][c]  (ld 512), cols>=510 zero
__device__ float g_ST[512 * 128];     // ST[k][m] (ld 128), rows>=510 zero
__device__ float g_P0[512 * 128];     // K-half partials of B*S^T
__device__ float g_P1[512 * 128];
__device__ float g_Cp[4 * 128 * 128]; // K-quarter partials of S*P
__device__ float g_U [128 * 512];     // ((sum Cq) ⊙ W) * S
__device__ float g_W [128 * 128];     // spectral weights
__device__ unsigned g_bar[NCTA + 1];  // [cta]=arrive, [NCTA]=release

__device__ __forceinline__ unsigned ld_acq(const unsigned* p) {
    unsigned v;
    asm volatile("ld.acquire.gpu.u32 %0, [%1];" : "=r"(v) : "l"(p) : "memory");
    return v;
}
__device__ __forceinline__ void st_rel(unsigned* p, unsigned v) {
    asm volatile("st.release.gpu.u32 [%0], %1;" :: "l"(p), "r"(v) : "memory");
}
__device__ __forceinline__ int modeI(int m) { return (m < 64) ? (m + 1) : (m + 383); }
__device__ __forceinline__ float4 ld4(const float* p) { return *(const float4*)p; }

__device__ __forceinline__ void grid_bar(unsigned ep) {
    __syncthreads();
    const int cta = blockIdx.x, tid = threadIdx.x;
    if (cta == 0) {
        if (tid > 0 && tid < NCTA)
            while (ld_acq(&g_bar[tid]) < ep) { }
        __syncthreads();
        if (tid == 0) st_rel(&g_bar[NCTA], ep);
    } else {
        if (tid == 0) {
            st_rel(&g_bar[cta], ep);
            while (ld_acq(&g_bar[NCTA]) < ep) { }
        }
        __syncthreads();
    }
}

#define GF_AFUSE 1   // A-load = (C0+C1+C2+C3) ⊙ W
#define GF_BFUSE 2   // B-load = P0 + P1
#define GF_SHIFT 4   // store to out[(r+1)][(c+1)], r,c<510

// One 32x32 output tile, 256 threads, 2x2 acc/thread, BK=16, prefetched.
template<int F>
__device__ void gemm_tile(const float* __restrict__ A, int lda,
                          const float* __restrict__ Bop, int ldb,
                          float* __restrict__ Cout, int ldc,
                          int mT, int nT, int kbase, int Klen,
                          float (*As)[36], float (*Bs)[36]) {
    const int tid = threadIdx.x;
    const int am = tid >> 2, akq = (tid & 3) * 4;            // tid<128: A loader
    const int bu = tid - 128;
    const int bk = bu >> 3, bnq = (bu & 7) * 4;              // tid>=128: B loader

    auto loadA = [&](int k) -> float4 {
        if (F & GF_AFUSE) {
            const float* p = A + (size_t)(mT + am) * lda + k;
            float4 c0 = ld4(p), c1 = ld4(p + 16384), c2 = ld4(p + 32768), c3 = ld4(p + 49152);
            float4 w = ld4(&g_W[(mT + am) * 128 + k]);
            return make_float4(((c0.x + c1.x) + (c2.x + c3.x)) * w.x,
                               ((c0.y + c1.y) + (c2.y + c3.y)) * w.y,
                               ((c0.z + c1.z) + (c2.z + c3.z)) * w.z,
                               ((c0.w + c1.w) + (c2.w + c3.w)) * w.w);
        }
        return ld4(A + (size_t)(mT + am) * lda + k);
    };
    auto loadB = [&](int k) -> float4 {
        const float* p = Bop + (size_t)k * ldb + nT + bnq;
        if (F & GF_BFUSE) {
            float4 u = ld4(p), v = ld4(p + 65536);
            return make_float4(u.x + v.x, u.y + v.y, u.z + v.z, u.w + v.w);
        }
        return ld4(p);
    };

    float4 a4, b4;
    if (tid < 128) a4 = loadA(kbase + akq);
    else           b4 = loadB(kbase + bk);

    float acc00 = 0.f, acc01 = 0.f, acc10 = 0.f, acc11 = 0.f;
    const int ty2 = (tid >> 4) * 2, tx2 = (tid & 15) * 2;

    for (int k0 = 0; k0 < Klen; k0 += 16) {
        __syncthreads();                   // prev compute done before overwrite
        if (tid < 128) {
            As[akq + 0][am] = a4.x; As[akq + 1][am] = a4.y;
            As[akq + 2][am] = a4.z; As[akq + 3][am] = a4.w;
        } else {
            *(float4*)&Bs[bk][bnq] = b4;
        }
        __syncthreads();
        if (k0 + 16 < Klen) {              // prefetch next chunk under compute
            if (tid < 128) a4 = loadA(kbase + k0 + 16 + akq);
            else           b4 = loadB(kbase + k0 + 16 + bk);
        }
#pragma unroll
        for (int kk = 0; kk < 16; kk++) {
            float2 av = *(const float2*)&As[kk][ty2];
            float2 bv = *(const float2*)&Bs[kk][tx2];
            acc00 += av.x * bv.x; acc01 += av.x * bv.y;
            acc10 += av.y * bv.x; acc11 += av.y * bv.y;
        }
    }

    if (F & GF_SHIFT) {
        const int r0 = mT + ty2, c0 = nT + tx2;
        if (r0 < 510) {
            if (c0     < 510) Cout[(r0 + 1) * 512 + c0 + 1] = acc00;
            if (c0 + 1 < 510) Cout[(r0 + 1) * 512 + c0 + 2] = acc01;
        }
        if (r0 + 1 < 510) {
            if (c0     < 510) Cout[(r0 + 2) * 512 + c0 + 1] = acc10;
            if (c0 + 1 < 510) Cout[(r0 + 2) * 512 + c0 + 2] = acc11;
        }
    } else {
        *(float2*)&Cout[(size_t)(mT + ty2)     * ldc + nT + tx2] = make_float2(acc00, acc01);
        *(float2*)&Cout[(size_t)(mT + ty2 + 1) * ldc + nT + tx2] = make_float2(acc10, acc11);
    }
}

__global__ void __launch_bounds__(TPB, 1)
jacobi_fused(const float* __restrict__ X, const float* __restrict__ Y,
             float* __restrict__ out) {
    __shared__ float As[16][36];
    __shared__ float Bs[16][36];
    const int cta = blockIdx.x, tid = threadIdx.x;
    const int gtid = cta * TPB + tid;
    const unsigned eb = __ldcg(&g_bar[NCTA]);   // epoch base (persists across replays)

    // ---- Stage A: x0, sine basis, W, out boundary ----
    for (int i = gtid; i < 512 * 512; i += GT) {
        float dx = X[i] - 0.5f, dy = Y[i] - 0.5f;
        g_x0[i] = expf(-50.0f * (dx * dx + dy * dy));
    }
    for (int i = gtid; i < 512 * 128; i += GT) {       // ST[k][m], ld 128
        int k = i >> 7, m = i & 127;
        float v = 0.0f;
        if (k < 510) {
            int a = (modeI(m) * (k + 1)) % 1022;       // exact reduction
            v = sinpif((float)a * (1.0f / 511.0f));
        }
        g_ST[i] = v;
    }
    for (int i = gtid; i < 128 * 512; i += GT) {       // S[m][c], ld 512
        int m = i >> 9, c = i & 511;
        float v = 0.0f;
        if (c < 510) {
            int a = (modeI(m) * (c + 1)) % 1022;
            v = sinpif((float)a * (1.0f / 511.0f));
        }
        g_S[i] = v;
    }
    for (int i = gtid; i < 128 * 128; i += GT) {       // W via fp64 binary pow
        int m = i >> 7, n = i & 127;
        double lam = 0.5 * (cospi((double)modeI(m) / 511.0)
                          + cospi((double)modeI(n) / 511.0));
        double r = 1.0, b = lam; int e = 999;
        while (e) { if (e & 1) r *= b; b *= b; e >>= 1; }
        g_W[i] = (float)(r * (4.0 / (511.0 * 511.0)));
    }
    for (int i = gtid; i < 2048; i += GT) {            // zero out boundary
        int e = i >> 9, t = i & 511;
        if      (e == 0) out[t] = 0.0f;
        else if (e == 1) out[511 * 512 + t] = 0.0f;
        else if (e == 2) out[t * 512] = 0.0f;
        else             out[t * 512 + 511] = 0.0f;
    }
    grid_bar(eb + 1);

    // ---- Stage B: B = one exact stencil step of x0 (interior), zero pad ----
    for (int i = gtid; i < 512 * 512; i += GT) {
        int k = i >> 9, j = i & 511;
        float v = 0.0f;
        if (k < 510 && j < 510) {
            int r = k + 1, c = j + 1;
            v = 0.25f * (((g_x0[(r - 1) * 512 + c] + g_x0[(r + 1) * 512 + c])
                          + g_x0[r * 512 + c - 1]) + g_x0[r * 512 + c + 1]);
        }
        g_B[i] = v;
    }
    grid_bar(eb + 2);

    // ---- G1: P = B * S^T (512x128, K=512), split-K2 -> 128 jobs ----
    for (int j = cta; j < 128; j += NCTA) {
        int t = j >> 1, h = j & 1;
        int mT = (t >> 2) * 32, nT = (t & 3) * 32;
        gemm_tile<0>(g_B, 512, g_ST, 128, h ? g_P1 : g_P0, 128,
                     mT, nT, h * 256, 256, As, Bs);
    }
    grid_bar(eb + 3);

    // ---- G2: Cq = S * (P0+P1) (128x128, K=512), split-K4 -> 64 jobs ----
    for (int j = cta; j < 64; j += NCTA) {
        int t = j >> 2, q = j & 3;
        int mT = (t >> 2) * 32, nT = (t & 3) * 32;
        gemm_tile<GF_BFUSE>(g_S, 512, g_P0, 128, g_Cp + q * 16384, 128,
                            mT, nT, q * 128, 128, As, Bs);
    }
    grid_bar(eb + 4);

    // ---- G3: U = ((C0+C1+C2+C3) ⊙ W) * S (128x512, K=128) -> 64 jobs ----
    for (int j = cta; j < 64; j += NCTA) {
        int mT = (j >> 4) * 32, nT = (j & 15) * 32;
        gemm_tile<GF_AFUSE>(g_Cp, 128, g_S, 512, g_U, 512,
                            mT, nT, 0, 128, As, Bs);
    }
    grid_bar(eb + 5);

    // ---- G4: out_int = S^T * U (512x512, K=128), shifted -> 256 jobs ----
    for (int j = cta; j < 256; j += NCTA) {
        int mT = (j >> 4) * 32, nT = (j & 15) * 32;
        gemm_tile<GF_SHIFT>(g_ST, 128, g_U, 512, out, 512,
                            mT, nT, 0, 128, As, Bs);
    }
}

extern "C" void kernel_launch(void* const* d_in, const int* in_sizes, int n_in,
                              void* d_out, int out_size) {
    (void)in_sizes; (void)n_in; (void)out_size;
    jacobi_fused<<<NCTA, TPB>>>((const float*)d_in[0], (const float*)d_in[1],
                                (float*)d_out);
}

// round 6
// speedup vs baseline: 60.0948x; 1.2226x over previous
#include <cuda_runtime.h>
#include <math.h>

// Spectral solution of 1000 masked-Jacobi steps on 512x512, ONE persistent
// kernel:  out_int = S^T * ( W ⊙ (S * B * S^T) ) * S
// B = interior of one exact stencil step of x0 (step 1 reads unmasked x0
// boundary), W = (2/511)^2 * lam^999. Only 128 modes/dim survive lam^999:
// I(m)=m+1 (m<64), m+383 (else).
// Round 6: 4x4 register blocking (FMA:LDS 8:1) and EVERY stage = 128 jobs:
//  G1: P_h = B*S^T        16 tiles(64x64) x splitK8          -> 128 jobs
//  G2: Cq_h = S*(sum P_h) 16 tiles(32x32) x splitK8, B-fuse8 -> 128 jobs
//  G3: U_h = ((sum Cq)⊙W)*S 64 tiles(32x32) x splitK2, A-fuse -> 128 jobs
//  G4: out = S^T*(U0+U1)  128 tiles(64x32), B-fuse2, shifted -> 128 jobs
// Grid barrier: per-CTA slots + CTA0 aggregation; epochs continue across
// graph replays (base read from release word) -> no reset node needed.

#define NCTA 128
#define TPB  256
#define GT   (NCTA * TPB)

__device__ float g_x0[512 * 512];
__device__ float g_B [512 * 512];      // stencil(x0) interior, zero padded
__device__ float g_S [128 * 512];      // S[m][c], ld 512 (cols>=510 zero)
__device__ float g_ST[512 * 128];      // ST[k][m], ld 128 (rows>=510 zero)
__device__ float g_P [8 * 512 * 128];  // G1 K-partials
__device__ float g_Cq[8 * 128 * 128];  // G2 K-partials
__device__ float g_U [2 * 128 * 512];  // G3 K-partials
__device__ float g_W [128 * 128];      // spectral weights
__device__ unsigned g_bar[NCTA + 1];

__device__ __forceinline__ unsigned ld_acq(const unsigned* p) {
    unsigned v;
    asm volatile("ld.acquire.gpu.u32 %0, [%1];" : "=r"(v) : "l"(p) : "memory");
    return v;
}
__device__ __forceinline__ void st_rel(unsigned* p, unsigned v) {
    asm volatile("st.release.gpu.u32 [%0], %1;" :: "l"(p), "r"(v) : "memory");
}
__device__ __forceinline__ int modeI(int m) { return (m < 64) ? (m + 1) : (m + 383); }
__device__ __forceinline__ float4 ld4(const float* p) { return *(const float4*)p; }

__device__ __forceinline__ void grid_bar(unsigned ep) {
    __syncthreads();
    const int cta = blockIdx.x, tid = threadIdx.x;
    if (cta == 0) {
        if (tid > 0 && tid < NCTA)
            while (ld_acq(&g_bar[tid]) < ep) { }
        __syncthreads();
        if (tid == 0) st_rel(&g_bar[NCTA], ep);
    } else {
        if (tid == 0) {
            st_rel(&g_bar[cta], ep);
            while (ld_acq(&g_bar[NCTA]) < ep) { }
        }
        __syncthreads();
    }
}

#define GF_AFUSE8 1   // A-load = (Cq0+..+Cq7) ⊙ W   (lda=128)
#define GF_BFUSE8 2   // B-load = P0+..+P7           (stride 65536)
#define GF_BFUSE2 4   // B-load = U0+U1              (stride 65536)
#define GF_SHIFT  8   // store out[(r+1)][(c+1)], r,c<510

#define SMS 68        // smem row stride (floats): 272B = 17*16 -> 16B aligned

// One BMxBN tile, 256 threads as 16x16, TM x TN accumulators, BK=16,
// register-prefetched smem pipeline.
template<int BM, int BN, int TM, int TN, int F>
__device__ void gemm_tile(const float* __restrict__ A, int lda,
                          const float* __restrict__ Bop, int ldb,
                          float* __restrict__ Cout, int ldc,
                          int mT, int nT, int kbase, int Klen,
                          float* __restrict__ As, float* __restrict__ Bs) {
    const int tid = threadIdx.x;
    const int tx = tid & 15, ty = tid >> 4;

    // loader assignments
    const int am = tid >> 2, ak = (tid & 3) * 4;           // A: row, k-quad
    const bool doA = (BM == 64) ? true : (tid < 128);
    int bk, bn; bool doB;
    if (BN == 64)      { bk = tid >> 4;        bn = (tid & 15) * 4; doB = true; }
    else if (BM == 64) { bk = tid >> 3;        bn = (tid & 7) * 4;  doB = (tid < 128); }
    else               { int u = tid - 128;
                         bk = u >> 3;          bn = (u & 7) * 4;    doB = (tid >= 128); }

    auto loadA = [&](int k) -> float4 {
        const float* p = A + (size_t)(mT + am) * lda + k;
        if (F & GF_AFUSE8) {
            float4 s = ld4(p);
#pragma unroll
            for (int h = 1; h < 8; h++) {
                float4 c = ld4(p + h * 16384);
                s.x += c.x; s.y += c.y; s.z += c.z; s.w += c.w;
            }
            float4 w = ld4(&g_W[(mT + am) * 128 + k]);
            return make_float4(s.x * w.x, s.y * w.y, s.z * w.z, s.w * w.w);
        }
        return ld4(p);
    };
    auto loadB = [&](int k) -> float4 {
        const float* p = Bop + (size_t)k * ldb + nT + bn;
        if (F & GF_BFUSE8) {
            float4 s = ld4(p);
#pragma unroll
            for (int h = 1; h < 8; h++) {
                float4 c = ld4(p + h * 65536);
                s.x += c.x; s.y += c.y; s.z += c.z; s.w += c.w;
            }
            return s;
        }
        if (F & GF_BFUSE2) {
            float4 u = ld4(p), v = ld4(p + 65536);
            return make_float4(u.x + v.x, u.y + v.y, u.z + v.z, u.w + v.w);
        }
        return ld4(p);
    };

    float4 a4, b4;
    if (doA) a4 = loadA(kbase + ak);
    if (doB) b4 = loadB(kbase + bk);

    float acc[TM][TN];
#pragma unroll
    for (int i = 0; i < TM; i++)
#pragma unroll
        for (int j = 0; j < TN; j++) acc[i][j] = 0.0f;

    for (int k0 = 0; k0 < Klen; k0 += 16) {
        __syncthreads();
        if (doA) {
            As[(ak + 0) * SMS + am] = a4.x;
            As[(ak + 1) * SMS + am] = a4.y;
            As[(ak + 2) * SMS + am] = a4.z;
            As[(ak + 3) * SMS + am] = a4.w;
        }
        if (doB) *(float4*)&Bs[bk * SMS + bn] = b4;
        __syncthreads();
        if (k0 + 16 < Klen) {
            if (doA) a4 = loadA(kbase + k0 + 16 + ak);
            if (doB) b4 = loadB(kbase + k0 + 16 + bk);
        }
#pragma unroll
        for (int kk = 0; kk < 16; kk++) {
            float a[TM], b[TN];
            if (TM == 4) {
                float4 v = *(const float4*)&As[kk * SMS + ty * 4];
                a[0] = v.x; a[1] = v.y; a[2] = v.z; a[3] = v.w;
            } else {
                float2 v = *(const float2*)&As[kk * SMS + ty * 2];
                a[0] = v.x; a[1] = v.y;
            }
            if (TN == 4) {
                float4 v = *(const float4*)&Bs[kk * SMS + tx * 4];
                b[0] = v.x; b[1] = v.y; b[2] = v.z; b[3] = v.w;
            } else {
                float2 v = *(const float2*)&Bs[kk * SMS + tx * 2];
                b[0] = v.x; b[1] = v.y;
            }
#pragma unroll
            for (int i = 0; i < TM; i++)
#pragma unroll
                for (int j = 0; j < TN; j++) acc[i][j] += a[i] * b[j];
        }
    }

    if (F & GF_SHIFT) {
#pragma unroll
        for (int i = 0; i < TM; i++) {
            int r = mT + ty * TM + i;
            if (r >= 510) continue;
#pragma unroll
            for (int j = 0; j < TN; j++) {
                int c = nT + tx * TN + j;
                if (c < 510) Cout[(r + 1) * 512 + c + 1] = acc[i][j];
            }
        }
    } else {
#pragma unroll
        for (int i = 0; i < TM; i++) {
            float* p = Cout + (size_t)(mT + ty * TM + i) * ldc + nT + tx * TN;
            if (TN == 4) *(float4*)p = make_float4(acc[i][0], acc[i][1], acc[i][2], acc[i][3]);
            else         *(float2*)p = make_float2(acc[i][0], acc[i][1]);
        }
    }
}

__global__ void __launch_bounds__(TPB, 1)
jacobi_fused(const float* __restrict__ X, const float* __restrict__ Y,
             float* __restrict__ out) {
    __shared__ float As[16 * SMS];
    __shared__ float Bs[16 * SMS];
    const int cta = blockIdx.x, tid = threadIdx.x;
    const int gtid = cta * TPB + tid;
    const unsigned eb = __ldcg(&g_bar[NCTA]);

    // ---- Stage A: x0, sine basis, W, out boundary ----
    for (int i = gtid; i < 512 * 512; i += GT) {
        float dx = X[i] - 0.5f, dy = Y[i] - 0.5f;
        g_x0[i] = expf(-50.0f * (dx * dx + dy * dy));
    }
    for (int i = gtid; i < 512 * 128; i += GT) {
        int k = i >> 7, m = i & 127;
        float v = 0.0f;
        if (k < 510) {
            int a = (modeI(m) * (k + 1)) % 1022;
            v = sinpif((float)a * (1.0f / 511.0f));
        }
        g_ST[i] = v;
    }
    for (int i = gtid; i < 128 * 512; i += GT) {
        int m = i >> 9, c = i & 511;
        float v = 0.0f;
        if (c < 510) {
            int a = (modeI(m) * (c + 1)) % 1022;
            v = sinpif((float)a * (1.0f / 511.0f));
        }
        g_S[i] = v;
    }
    for (int i = gtid; i < 128 * 128; i += GT) {
        int m = i >> 7, n = i & 127;
        double lam = 0.5 * (cospi((double)modeI(m) / 511.0)
                          + cospi((double)modeI(n) / 511.0));
        double r = 1.0, b = lam; int e = 999;
        while (e) { if (e & 1) r *= b; b *= b; e >>= 1; }
        g_W[i] = (float)(r * (4.0 / (511.0 * 511.0)));
    }
    for (int i = gtid; i < 2048; i += GT) {
        int e = i >> 9, t = i & 511;
        if      (e == 0) out[t] = 0.0f;
        else if (e == 1) out[511 * 512 + t] = 0.0f;
        else if (e == 2) out[t * 512] = 0.0f;
        else             out[t * 512 + 511] = 0.0f;
    }
    grid_bar(eb + 1);

    // ---- Stage B: B = one exact stencil step of x0, zero padded ----
    for (int i = gtid; i < 512 * 512; i += GT) {
        int k = i >> 9, j = i & 511;
        float v = 0.0f;
        if (k < 510 && j < 510) {
            int r = k + 1, c = j + 1;
            v = 0.25f * (((g_x0[(r - 1) * 512 + c] + g_x0[(r + 1) * 512 + c])
                          + g_x0[r * 512 + c - 1]) + g_x0[r * 512 + c + 1]);
        }
        g_B[i] = v;
    }
    grid_bar(eb + 2);

    // ---- G1: P_h = B * S^T, 16 tiles(64x64) x splitK8 ----
    {
        int t = cta >> 3, h = cta & 7;
        gemm_tile<64, 64, 4, 4, 0>(g_B, 512, g_ST, 128,
                                   g_P + h * 65536, 128,
                                   (t >> 1) * 64, (t & 1) * 64, h * 64, 64, As, Bs);
    }
    grid_bar(eb + 3);

    // ---- G2: Cq_h = S * (sum P), 16 tiles(32x32) x splitK8, B-fuse8 ----
    {
        int t = cta >> 3, h = cta & 7;
        gemm_tile<32, 32, 2, 2, GF_BFUSE8>(g_S, 512, g_P, 128,
                                           g_Cq + h * 16384, 128,
                                           (t >> 2) * 32, (t & 3) * 32, h * 64, 64, As, Bs);
    }
    grid_bar(eb + 4);

    // ---- G3: U_h = ((sum Cq) ⊙ W) * S, 64 tiles(32x32) x splitK2, A-fuse ----
    {
        int t = cta >> 1, h = cta & 1;
        gemm_tile<32, 32, 2, 2, GF_AFUSE8>(g_Cq, 128, g_S, 512,
                                           g_U + h * 65536, 512,
                                           (t >> 4) * 32, (t & 15) * 32, h * 64, 64, As, Bs);
    }
    grid_bar(eb + 5);

    // ---- G4: out = S^T * (U0+U1), 128 tiles(64x32), shifted store ----
    {
        gemm_tile<64, 32, 4, 2, GF_BFUSE2 | GF_SHIFT>(g_ST, 128, g_U, 512,
                                                      out, 512,
                                                      (cta >> 4) * 64, (cta & 15) * 32,
                                                      0, 128, As, Bs);
    }
}

extern "C" void kernel_launch(void* const* d_in, const int* in_sizes, int n_in,
                              void* d_out, int out_size) {
    (void)in_sizes; (void)n_in; (void)out_size;
    jacobi_fused<<<NCTA, TPB>>>((const float*)d_in[0], (const float*)d_in[1],
                                (float*)d_out);
}